// round 10
// baseline (speedup 1.0000x reference)
#include <cuda_runtime.h>
#include <cuda_fp16.h>
#include <cstdint>
#include <cstring>

#define D_DIM   11008
#define K_DIM   172
#define NKB     11           // k16 blocks for GEMM-1 (j = 0..175)
#define BP      72           // smem row pitch in uint32 (288B) — bank-verified
#define THREADS 128
// Bs: 88 pair-rows (Xr) + Hs: 32 pair-rows (H_64), same pitch
#define SMEM_BYTES ((88 + 32) * BP * 4)   // 34560

static __device__ __forceinline__ uint32_t h2_bits(__half2 h) {
    uint32_t u;
    memcpy(&u, &h, 4);
    return u;
}

// had_K * (1/sqrt(D)) pre-packed into fp16 m16n8k16 A-fragment order (R9 layout):
//   block (mw, t, kb) -> 32 lanes -> uint4 {a0, a1, a2, a3}, one LDG.128 per (t,kb).
__device__ uint4 g_hKh[4 * 3 * NKB * 32];

__global__ void prep_hk(const float* __restrict__ hK) {
    int idx = blockIdx.x * blockDim.x + threadIdx.x;
    if (idx >= 4 * 3 * NKB * 32) return;
    int lane = idx & 31;
    int kb   = (idx >> 5) % NKB;
    int t    = (idx >> 5) / NKB % 3;
    int mw   = (idx >> 5) / (NKB * 3);
    int q = lane >> 2, p = lane & 3;
    int i  = mw * 48 + t * 16 + q;
    int k0 = 16 * kb + 2 * p;
    const float scale = rsqrtf((float)D_DIM);   // fold 1/sqrt(D) into hK
    float f[8];
    #pragma unroll
    for (int e = 0; e < 8; ++e) {
        int ii = i + ((e >> 1) & 1) * 8;
        int kk = k0 + (e >> 2) * 8 + (e & 1);
        f[e] = (ii < K_DIM && kk < K_DIM) ? hK[ii * K_DIM + kk] * scale : 0.f;
    }
    uint4 r;
    r.x = h2_bits(__floats2half2_rn(f[0], f[1]));
    r.y = h2_bits(__floats2half2_rn(f[2], f[3]));
    r.z = h2_bits(__floats2half2_rn(f[4], f[5]));
    r.w = h2_bits(__floats2half2_rn(f[6], f[7]));
    g_hKh[idx] = r;
}

__global__ __launch_bounds__(THREADS, 3)
void had_mma_kernel(const float* __restrict__ x,
                    float* __restrict__ out)
{
    extern __shared__ uint32_t Bs[];   // [88][BP] Xr half2-pairs, then [32][BP] H_64 half2-pairs
    uint32_t* Hs = Bs + 88 * BP;
    const int tid  = threadIdx.x;
    const int w    = tid >> 5;               // 0..3
    const int lane = tid & 31;
    const int q    = lane >> 2;              // 0..7
    const int p    = lane & 3;               // 0..3
    const int row  = blockIdx.x;

    // ---------- Phase 0: build H_64 fragment table (pair-packed over m') ----------
    // Hs[j2][m] = {H[2j2][m], H[2j2+1][m]},  H[a][b] = (-1)^popc(a&b)
    for (int idx = tid; idx < 32 * 64; idx += THREADS) {
        int j2 = idx >> 6, m = idx & 63;
        float h0 = (__popc((2 * j2) & m) & 1) ? -1.f : 1.f;
        float h1 = (__popc((2 * j2 + 1) & m) & 1) ? -1.f : 1.f;
        Hs[j2 * BP + m] = h2_bits(__floats2half2_rn(h0, h1));
    }

    // ---------- Phase 1: load raw Xr -> half2 pair-packed Bs (NO FWHT!) ----------
    // pair c2 = w + 4*k2; chunks 2c2, 2c2+1; c2 >= 86 -> zero pad rows.
    {
        const float* xr = x + (size_t)row * D_DIM;
        #pragma unroll
        for (int k2 = 0; k2 < 22; ++k2) {
            const int c2 = w + 4 * k2;
            float c0 = 0.f, c1 = 0.f, d0 = 0.f, d1 = 0.f;
            if (c2 < 86) {
                const float* b0 = xr + (size_t)c2 * 128 + lane;
                c0 = b0[0]; c1 = b0[32]; d0 = b0[64]; d1 = b0[96];
            }
            Bs[c2 * BP + lane]      = h2_bits(__floats2half2_rn(c0, d0));  // m = lane
            Bs[c2 * BP + lane + 32] = h2_bits(__floats2half2_rn(c1, d1));  // m = lane+32
        }
    }
    __syncthreads();

    // ---------- Phase 2a: T = (hK/sqrtD) @ Xr  via m16n8k16 fp16 ----------
    const int mw = w;                        // i0 = mw*48; warp covers all 64 cols

    float acc[3][8][4];
    #pragma unroll
    for (int t = 0; t < 3; ++t)
        #pragma unroll
        for (int u = 0; u < 8; ++u)
            #pragma unroll
            for (int r = 0; r < 4; ++r) acc[t][u][r] = 0.f;

    const uint4* Aw = g_hKh + (size_t)(mw * 3) * NKB * 32 + lane;

    #pragma unroll 2
    for (int kb = 0; kb < NKB; ++kb) {
        uint32_t b0[8], b1[8];
        const uint32_t* br = Bs + (8 * kb + p) * BP + q;
        #pragma unroll
        for (int u = 0; u < 8; ++u) {
            b0[u] = br[8 * u];                // k = 16kb+2p, +1
            b1[u] = br[8 * u + 4 * BP];       // k = 16kb+2p+8, +9
        }
        #pragma unroll
        for (int t = 0; t < 3; ++t) {
            uint4 a = Aw[(size_t)(t * NKB + kb) * 32];   // one coalesced LDG.128
            #pragma unroll
            for (int u = 0; u < 8; ++u) {
                asm volatile(
                    "mma.sync.aligned.m16n8k16.row.col.f32.f16.f16.f32 "
                    "{%0,%1,%2,%3}, {%4,%5,%6,%7}, {%8,%9}, {%0,%1,%2,%3};"
                    : "+f"(acc[t][u][0]), "+f"(acc[t][u][1]),
                      "+f"(acc[t][u][2]), "+f"(acc[t][u][3])
                    : "r"(a.x), "r"(a.y), "r"(a.z), "r"(a.w),
                      "r"(b0[u]), "r"(b1[u]));
            }
        }
    }

    // ---------- Phase 2b: out = T @ H_64, A-fragments register-direct from acc ----------
    // C-fragment of acc IS the A-fragment of T: a0 = {C[q][16v+2p], C[q][16v+2p+1]} etc.
    {
        float* orow = out + (size_t)row * D_DIM;
        const int i0 = mw * 48;
        #pragma unroll
        for (int t = 0; t < 3; ++t) {
            float a2c[8][4];
            #pragma unroll
            for (int u = 0; u < 8; ++u)
                #pragma unroll
                for (int r = 0; r < 4; ++r) a2c[u][r] = 0.f;

            #pragma unroll
            for (int v = 0; v < 4; ++v) {
                const uint32_t a0 = h2_bits(__floats2half2_rn(acc[t][2*v  ][0], acc[t][2*v  ][1]));
                const uint32_t a1 = h2_bits(__floats2half2_rn(acc[t][2*v  ][2], acc[t][2*v  ][3]));
                const uint32_t a2 = h2_bits(__floats2half2_rn(acc[t][2*v+1][0], acc[t][2*v+1][1]));
                const uint32_t a3 = h2_bits(__floats2half2_rn(acc[t][2*v+1][2], acc[t][2*v+1][3]));
                const uint32_t* hr = Hs + (8 * v + p) * BP + q;
                #pragma unroll
                for (int u = 0; u < 8; ++u) {
                    const uint32_t hb0 = hr[8 * u];               // m' = 16v+2p, +1
                    const uint32_t hb1 = hr[8 * u + 4 * BP];      // m' = 16v+2p+8, +9
                    asm volatile(
                        "mma.sync.aligned.m16n8k16.row.col.f32.f16.f16.f32 "
                        "{%0,%1,%2,%3}, {%4,%5,%6,%7}, {%8,%9}, {%0,%1,%2,%3};"
                        : "+f"(a2c[u][0]), "+f"(a2c[u][1]),
                          "+f"(a2c[u][2]), "+f"(a2c[u][3])
                        : "r"(a0), "r"(a1), "r"(a2), "r"(a3),
                          "r"(hb0), "r"(hb1));
                }
            }
            // direct store (R5-proven pattern: 8-row x 32B runs)
            const int ib = i0 + t * 16 + q;
            #pragma unroll
            for (int u = 0; u < 8; ++u) {
                const int m = u * 8 + 2 * p;
                if (ib < K_DIM)
                    *(float2*)(orow + ib * 64 + m) = make_float2(a2c[u][0], a2c[u][1]);
                if (ib + 8 < K_DIM)
                    *(float2*)(orow + (ib + 8) * 64 + m) = make_float2(a2c[u][2], a2c[u][3]);
            }
        }
    }
}

extern "C" void kernel_launch(void* const* d_in, const int* in_sizes, int n_in,
                              void* d_out, int out_size)
{
    const float* x  = (const float*)d_in[0];
    const float* hK = (const float*)d_in[1];
    int nx = in_sizes[0];
    if (n_in > 1 && in_sizes[0] == K_DIM * K_DIM) {   // defensive input-order check
        x  = (const float*)d_in[1];
        hK = (const float*)d_in[0];
        nx = in_sizes[1];
    }
    float* out = (float*)d_out;
    const int nrows = nx / D_DIM;

    cudaFuncSetAttribute(had_mma_kernel,
                         cudaFuncAttributeMaxDynamicSharedMemorySize, SMEM_BYTES);

    prep_hk<<<(4 * 3 * NKB * 32 + 255) / 256, 256>>>(hK);
    had_mma_kernel<<<nrows, THREADS, SMEM_BYTES>>>(x, out);
}